// round 1
// baseline (speedup 1.0000x reference)
#include <cuda_runtime.h>

#define BATCH       16384
#define NUM_FIELDS  20
#define NUM_FEAT    100000
#define LATENT      64

// One warp per batch row.
// Lane l handles latent dims [2l, 2l+1] -> each field gather is one coalesced
// 256B float2 warp load. All 20 gathers are independent (indices live in
// registers, broadcast via shfl), so unrolling gives MLP~20 per warp.
__global__ void __launch_bounds__(256, 8)
ffm_kernel(const int* __restrict__ x,
           const float* __restrict__ emb,
           float* __restrict__ out)
{
    const int warp = (blockIdx.x * blockDim.x + threadIdx.x) >> 5;
    const int lane = threadIdx.x & 31;
    if (warp >= BATCH) return;

    // Lanes 0..19 load this row's feature indices; also reused for the linear term.
    int xv = 0;
    if (lane < NUM_FIELDS) xv = __ldg(&x[warp * NUM_FIELDS + lane]);

    float2 s = make_float2(0.f, 0.f);
    float  ssq = 0.f;

    #pragma unroll
    for (int f = 0; f < NUM_FIELDS; f++) {
        const int idx = __shfl_sync(0xffffffffu, xv, f);
        const float2* p = reinterpret_cast<const float2*>(
            emb + ((size_t)f * NUM_FEAT + (size_t)idx) * LATENT) + lane;
        const float2 v = __ldg(p);
        s.x += v.x;
        s.y += v.y;
        ssq = fmaf(v.x, v.x, fmaf(v.y, v.y, ssq));
    }

    // Per-lane partial: sum_d s_d^2 - sum_{f,d} v^2 over this lane's 2 dims.
    float t   = fmaf(s.x, s.x, s.y * s.y) - ssq;
    float lin = (float)xv;   // lanes >= NUM_FIELDS contribute 0

    #pragma unroll
    for (int off = 16; off > 0; off >>= 1) {
        t   += __shfl_down_sync(0xffffffffu, t,   off);
        lin += __shfl_down_sync(0xffffffffu, lin, off);
    }

    if (lane == 0) out[warp] = lin + 0.5f * t;
}

extern "C" void kernel_launch(void* const* d_in, const int* in_sizes, int n_in,
                              void* d_out, int out_size)
{
    const int*   x   = (const int*)d_in[0];
    // d_in[1] = field_indices (0..19), unused: fields are implicit in layout.
    const float* emb = (const float*)d_in[2];
    float*       out = (float*)d_out;

    const int warps_per_block = 256 / 32;                 // 8
    const int blocks = (BATCH + warps_per_block - 1) / warps_per_block;  // 2048
    ffm_kernel<<<blocks, 256>>>(x, emb, out);
}